// round 15
// baseline (speedup 1.0000x reference)
#include <cuda_runtime.h>
#include <cstdint>

#define LV     4087
#define BROWS  2048
#define NSTEP  1021
#define EPSF   1e-6f

__device__ double   g_acc   = 0.0;
__device__ unsigned g_count = 0u;

__device__ __forceinline__ float dnbl(float v) { return ((v + 1.0f) * 0.5f) * 2.1f + 0.9f; }
__device__ __forceinline__ float dnd (float v) { return ((v + 1.0f) * 0.5f) * 3.5f + 1.5f; }
__device__ __forceinline__ float clip1(float v) { return fminf(fmaxf(v, -1.0f), 1.0f); }
__device__ __forceinline__ float clipE(float v) { return fminf(fmaxf(v, -1.0f + EPSF), 1.0f - EPSF); }
__device__ __forceinline__ float rcp_a(float x){ float y; asm("rcp.approx.f32 %0,%1;":"=f"(y):"f"(x)); return y; }
__device__ __forceinline__ float rsq_a(float x){ float y; asm("rsqrt.approx.f32 %0,%1;":"=f"(y):"f"(x)); return y; }
__device__ __forceinline__ float sqt_a(float x){ float y; asm("sqrt.approx.f32 %0,%1;":"=f"(y):"f"(x)); return y; }

// ---------------------------------------------------------------------------
// Affine algebra (col-major m[3c+r]); (L∘R) = (R_L·R_R, t_L + R_L·t_R)
// ---------------------------------------------------------------------------
struct Aff { float m[9]; float p[3]; };

__device__ __forceinline__ void mv(const float* m, float x, float y, float z, float* o)
{
    o[0] = fmaf(m[0], x, fmaf(m[3], y, m[6] * z));
    o[1] = fmaf(m[1], x, fmaf(m[4], y, m[7] * z));
    o[2] = fmaf(m[2], x, fmaf(m[5], y, m[8] * z));
}
__device__ __forceinline__ void compose(const Aff& L, const Aff& R, Aff& O)
{
    mv(L.m, R.m[0], R.m[1], R.m[2], O.m + 0);
    mv(L.m, R.m[3], R.m[4], R.m[5], O.m + 3);
    mv(L.m, R.m[6], R.m[7], R.m[8], O.m + 6);
    float tv[3];
    mv(L.m, R.p[0], R.p[1], R.p[2], tv);
    O.p[0] = L.p[0] + tv[0];
    O.p[1] = L.p[1] + tv[1];
    O.p[2] = L.p[2] + tv[2];
}
__device__ __forceinline__ void identityA(Aff& X)
{
    X.m[0] = 1.f; X.m[1] = 0.f; X.m[2] = 0.f;
    X.m[3] = 0.f; X.m[4] = 1.f; X.m[5] = 0.f;
    X.m[6] = 0.f; X.m[7] = 0.f; X.m[8] = 1.f;
    X.p[0] = X.p[1] = X.p[2] = 0.f;
}

// ---------------------------------------------------------------------------
// Shared memory:
//   pl   [48*128]   local translations -> overwritten with global positions
//   uni  [2*4620]   staging (stP|stT), ALIASED by KS array sh[2][12*128]
//   ish  [8], wred [8]
// ---------------------------------------------------------------------------
#define SPAD(a)  ((a) + ((a) >> 3))
#define STG_F    4620
#define UNI_F    (2 * STG_F)
#define PL_F     (48 * 128)
#define ISH_OFF  (PL_F + UNI_F)
#define WRED_OFF (ISH_OFF + 8)
#define SMEM_F   (WRED_OFF + 8)
#define SMEM_BYTES (SMEM_F * 4)

// ---------------------------------------------------------------------------
// Phase 1 for one chain (identical arithmetic to R14).
// ---------------------------------------------------------------------------
__device__ __forceinline__ void chain_phase1(const float* __restrict__ st, int t,
                                             float* __restrict__ plc, Aff& inc,
                                             float* __restrict__ ish_slot)
{
    const int j0 = 8 * t;
    float l_a = dnbl(st[SPAD(3064 + j0)]);
    float l_b = dnbl(st[SPAD(3064 + j0 + 1)]);
    float d_a = dnd (st[SPAD(2042 + j0)]);
    float ctp = clipE((l_a * l_a + l_b * l_b - d_a * d_a) * rcp_a(2.0f * l_a * l_b));
    float stp = sqt_a((1.0f - ctp) * (1.0f + ctp));
    if (t == 0) {
        ish_slot[0] = l_a; ish_slot[1] = l_b; ish_slot[2] = ctp; ish_slot[3] = stp;
    }
#pragma unroll
    for (int jj = 0; jj < 8; ++jj) {
        const int j = j0 + jj;
        float l_c = dnbl(st[SPAD(3064 + j + 2)]);
        float d_b = dnd (st[SPAD(2042 + j + 1)]);
        float ctc = clipE((l_b * l_b + l_c * l_c - d_b * d_b) * rcp_a(2.0f * l_b * l_c));
        float stc = sqt_a((1.0f - ctc) * (1.0f + ctc));

        float s0 = st[SPAD(2 * j)];
        float s1 = st[SPAD(2 * j + 1)];
        float h2 = s0 * s0 + s1 * s1;
        float cch, sch;
        if (h2 < 1e-30f) { cch = 1.0f; sch = 0.0f; }
        else { float rh = rsq_a(h2); cch = s1 * rh; sch = s0 * rh; }

        float sbc = l_b * rcp_a(l_b + EPSF);
        float cr  = l_a * sbc * stp;
        float sn  = cr * rcp_a(cr + EPSF);
        float sm  = sn * sbc;

        float wx = -l_c * ctc * sbc;
        float wy =  l_c * stc * cch * sm;
        float wz =  l_c * stc * sch * sn;
        if (j >= NSTEP) { ctc = -1.f; stc = 0.f; cch = 1.f; sch = 0.f; wx = wy = wz = 0.f; }

        Aff G;
        G.m[0] = -ctc;      G.m[1] = stc * cch;  G.m[2] = stc * sch;
        G.m[3] = -stc;      G.m[4] = -ctc * cch; G.m[5] = -ctc * sch;
        G.m[6] = 0.f;       G.m[7] = -sch;       G.m[8] = cch;
        G.p[0] = wx; G.p[1] = wy; G.p[2] = wz;

        if (jj == 0) inc = G;
        else { Aff n; compose(inc, G, n); inc = n; }

        plc[(jj * 3 + 0) * 128 + t] = inc.p[0];
        plc[(jj * 3 + 1) * 128 + t] = inc.p[1];
        plc[(jj * 3 + 2) * 128 + t] = inc.p[2];

        l_a = l_b; l_b = l_c; ctp = ctc; stp = stc;
    }
}

// ---------------------------------------------------------------------------
// Fused kernel: 256 threads/row. Half 0 = pred chain, half 1 = targ chain.
// ---------------------------------------------------------------------------
__global__ void __launch_bounds__(256) fused_kernel(const float* __restrict__ pred,
                                                    const float* __restrict__ targ,
                                                    float* __restrict__ out)
{
    extern __shared__ float smem[];
    float* pl   = smem;
    float* uni  = smem + PL_F;
    float* stP  = uni;
    float* stT  = uni + STG_F;
    float* sh   = uni;                 // aliases staging (used after phase 1)
    float* ish  = smem + ISH_OFF;
    float* wred = smem + WRED_OFF;

    const int tid  = threadIdx.x;
    const int half = tid >> 7;         // 0 = pred, 1 = targ
    const int t    = tid & 127;
    const int row  = blockIdx.x;
    const float* vp = pred + (size_t)row * LV;
    const float* vt = targ + (size_t)row * LV;

    // ---- stage inputs (coalesced, 256 threads); pred clipped at stage ----
    for (int i = tid; i < 4104; i += 256) {
        float a = (i < LV) ? clip1(__ldg(vp + i)) : 0.f;
        float b = (i < LV) ? __ldg(vt + i) : 0.f;
        stP[SPAD(i)] = a;
        stT[SPAD(i)] = b;
    }
    __syncthreads();

    // ---- phase 1: one chain per half ----
    const float* st = half ? stT : stP;
    float* plc = pl + half * (24 * 128);
    Aff inc;
    chain_phase1(st, t, plc, inc, ish + 4 * half);
    __syncthreads();   // all staging reads done -> sh may alias it

    // ---- phase 2: Kogge-Stone over 128 aggregates (per half) ----
    float* shc = sh + half * (12 * 128);
#pragma unroll
    for (int k = 0; k < 9; ++k) shc[k * 128 + t] = inc.m[k];
#pragma unroll
    for (int k = 0; k < 3; ++k) shc[(9 + k) * 128 + t] = inc.p[k];
    __syncthreads();

    for (int d = 1; d < 128; d <<= 1) {
        Aff o;
        int src = t - d;
        int s2  = src < 0 ? 0 : src;
#pragma unroll
        for (int k = 0; k < 9; ++k) o.m[k] = shc[k * 128 + s2];
#pragma unroll
        for (int k = 0; k < 3; ++k) o.p[k] = shc[(9 + k) * 128 + s2];
        __syncthreads();
        if (src >= 0) {
            Aff n;
            compose(o, inc, n);
            inc = n;
        }
#pragma unroll
        for (int k = 0; k < 9; ++k) shc[k * 128 + t] = inc.m[k];
#pragma unroll
        for (int k = 0; k < 3; ++k) shc[(9 + k) * 128 + t] = inc.p[k];
        __syncthreads();
    }

    // ---- exclusive prefix ----
    Aff ex;
    if (t == 0) identityA(ex);
    else {
#pragma unroll
        for (int k = 0; k < 9; ++k) ex.m[k] = shc[k * 128 + t - 1];
#pragma unroll
        for (int k = 0; k < 3; ++k) ex.p[k] = shc[(9 + k) * 128 + t - 1];
    }

    // ---- globalize with this chain's initial frame S = (F2, p2) ----
    float l0 = ish[4 * half + 0], l1 = ish[4 * half + 1];
    float c0 = ish[4 * half + 2], s0i = ish[4 * half + 3];
    Aff S;
    S.m[0] = -c0;  S.m[1] = s0i;  S.m[2] = 0.f;
    S.m[3] = -s0i; S.m[4] = -c0;  S.m[5] = 0.f;
    S.m[6] = 0.f;  S.m[7] = 0.f;  S.m[8] = 1.f;
    S.p[0] = fmaf(-l1, c0, l0); S.p[1] = l1 * s0i; S.p[2] = 0.f;
    Aff R;
    compose(S, ex, R);

    // ---- phase 3a: overwrite pl with GLOBAL positions (own slots) ----
#pragma unroll
    for (int jj = 0; jj < 8; ++jj) {
        float lx = plc[(jj * 3 + 0) * 128 + t];
        float ly = plc[(jj * 3 + 1) * 128 + t];
        float lz = plc[(jj * 3 + 2) * 128 + t];
        float e[3];
        mv(R.m, lx, ly, lz, e);
        plc[(jj * 3 + 0) * 128 + t] = R.p[0] + e[0];
        plc[(jj * 3 + 1) * 128 + t] = R.p[1] + e[1];
        plc[(jj * 3 + 2) * 128 + t] = R.p[2] + e[2];
    }
    __syncthreads();

    // ---- phase 3b: all 256 threads compute pred-targ diffs ----
    float acc = 0.f;
    if (tid == 0) {   // atoms 1 and 2 (atom 0 identical zero)
        float l0P = ish[0], l1P = ish[1], ct0 = ish[2], st0 = ish[3];
        float l0T = ish[4], l1T = ish[5], ct1 = ish[6], st1 = ish[7];
        float d1  = l0P - l0T;
        float d2x = fmaf(-l1P, ct0, l0P) - fmaf(-l1T, ct1, l0T);
        float d2y = l1P * st0 - l1T * st1;
        acc = fmaf(d1, d1, fmaf(d2x, d2x, d2y * d2y));
    }
#pragma unroll
    for (int i = 0; i < 4; ++i) {
        int idx = tid + 256 * i;           // (jj, t2) pair
        int jj  = idx >> 7;
        int t2  = idx & 127;
        if (8 * t2 + jj < NSTEP) {
            float fx = pl[(jj * 3 + 0) * 128 + t2] - pl[(24 * 128) + (jj * 3 + 0) * 128 + t2];
            float fy = pl[(jj * 3 + 1) * 128 + t2] - pl[(24 * 128) + (jj * 3 + 1) * 128 + t2];
            float fz = pl[(jj * 3 + 2) * 128 + t2] - pl[(24 * 128) + (jj * 3 + 2) * 128 + t2];
            acc = fmaf(fx, fx, acc);
            acc = fmaf(fy, fy, acc);
            acc = fmaf(fz, fz, acc);
        }
    }

    // ---- reduce + global accumulate; last block finalizes + self-resets ----
#pragma unroll
    for (int off = 16; off > 0; off >>= 1)
        acc += __shfl_xor_sync(0xffffffffu, acc, off);
    if ((tid & 31) == 0) wred[tid >> 5] = acc;
    __syncthreads();
    if (tid == 0) {
        float tot = 0.f;
#pragma unroll
        for (int w = 0; w < 8; ++w) tot += wred[w];
        atomicAdd(&g_acc, (double)tot);
        __threadfence();
        unsigned old = atomicAdd(&g_count, 1u);
        if (old == (unsigned)(gridDim.x - 1)) {
            double total;
            asm volatile("ld.global.cg.f64 %0, [%1];" : "=d"(total) : "l"(&g_acc));
            out[0] = (float)(total * (1.0 / (2048.0 * 1024.0 * 3.0)));
            asm volatile("st.global.cg.f64 [%0], %1;" :: "l"(&g_acc), "d"(0.0));
            __threadfence();
            asm volatile("st.global.cg.u32 [%0], %1;" :: "l"(&g_count), "r"(0u));
        }
    }
}

extern "C" void kernel_launch(void* const* d_in, const int* in_sizes, int n_in,
                              void* d_out, int out_size)
{
    const float* pred = (const float*)d_in[0];
    const float* targ = (const float*)d_in[1];
    float* out = (float*)d_out;

    cudaFuncSetAttribute(fused_kernel,
                         cudaFuncAttributeMaxDynamicSharedMemorySize, SMEM_BYTES);
    fused_kernel<<<BROWS, 256, SMEM_BYTES>>>(pred, targ, out);
}

// round 16
// speedup vs baseline: 1.0870x; 1.0870x over previous
#include <cuda_runtime.h>
#include <cstdint>

#define LV     4087
#define BROWS  2048
#define NSTEP  1021
#define EPSF   1e-6f

__device__ double   g_acc   = 0.0;
__device__ unsigned g_count = 0u;

__device__ __forceinline__ float dnbl(float v) { return ((v + 1.0f) * 0.5f) * 2.1f + 0.9f; }
__device__ __forceinline__ float dnd (float v) { return ((v + 1.0f) * 0.5f) * 3.5f + 1.5f; }
__device__ __forceinline__ float clip1(float v) { return fminf(fmaxf(v, -1.0f), 1.0f); }
__device__ __forceinline__ float clipE(float v) { return fminf(fmaxf(v, -1.0f + EPSF), 1.0f - EPSF); }
__device__ __forceinline__ float rcp_a(float x){ float y; asm("rcp.approx.f32 %0,%1;":"=f"(y):"f"(x)); return y; }
__device__ __forceinline__ float rsq_a(float x){ float y; asm("rsqrt.approx.f32 %0,%1;":"=f"(y):"f"(x)); return y; }
__device__ __forceinline__ float sqt_a(float x){ float y; asm("sqrt.approx.f32 %0,%1;":"=f"(y):"f"(x)); return y; }

// ---------------------------------------------------------------------------
// Affine algebra (col-major m[3c+r]); (L∘R) = (R_L·R_R, t_L + R_L·t_R)
// ---------------------------------------------------------------------------
struct Aff { float m[9]; float p[3]; };

__device__ __forceinline__ void mv(const float* m, float x, float y, float z, float* o)
{
    o[0] = fmaf(m[0], x, fmaf(m[3], y, m[6] * z));
    o[1] = fmaf(m[1], x, fmaf(m[4], y, m[7] * z));
    o[2] = fmaf(m[2], x, fmaf(m[5], y, m[8] * z));
}
__device__ __forceinline__ void compose(const Aff& L, const Aff& R, Aff& O)
{
    mv(L.m, R.m[0], R.m[1], R.m[2], O.m + 0);
    mv(L.m, R.m[3], R.m[4], R.m[5], O.m + 3);
    mv(L.m, R.m[6], R.m[7], R.m[8], O.m + 6);
    float tv[3];
    mv(L.m, R.p[0], R.p[1], R.p[2], tv);
    O.p[0] = L.p[0] + tv[0];
    O.p[1] = L.p[1] + tv[1];
    O.p[2] = L.p[2] + tv[2];
}
__device__ __forceinline__ void identityA(Aff& X)
{
    X.m[0] = 1.f; X.m[1] = 0.f; X.m[2] = 0.f;
    X.m[3] = 0.f; X.m[4] = 1.f; X.m[5] = 0.f;
    X.m[6] = 0.f; X.m[7] = 0.f; X.m[8] = 1.f;
    X.p[0] = X.p[1] = X.p[2] = 0.f;
}
__device__ __forceinline__ void shfl_up_aff(const Aff& in, Aff& o, int d)
{
#pragma unroll
    for (int k = 0; k < 9; ++k) o.m[k] = __shfl_up_sync(0xffffffffu, in.m[k], d);
#pragma unroll
    for (int k = 0; k < 3; ++k) o.p[k] = __shfl_up_sync(0xffffffffu, in.p[k], d);
}

// ---------------------------------------------------------------------------
// Shared memory:
//   pl   [48*128]   local translations -> overwritten with global positions
//   stg  [2*4620]   staging (stP|stT)
//   agg  [2*4*12]   warp aggregates (per half)
//   ish  [8], wred [8]
// ---------------------------------------------------------------------------
#define SPAD(a)  ((a) + ((a) >> 3))
#define STG_F    4620
#define PL_F     (48 * 128)
#define STG_OFF  PL_F
#define AGG_OFF  (STG_OFF + 2 * STG_F)
#define ISH_OFF  (AGG_OFF + 96)
#define WRED_OFF (ISH_OFF + 8)
#define SMEM_F   (WRED_OFF + 8)
#define SMEM_BYTES (SMEM_F * 4)

// ---------------------------------------------------------------------------
// Phase 1 for one chain (identical arithmetic to R14/R15).
// ---------------------------------------------------------------------------
__device__ __forceinline__ void chain_phase1(const float* __restrict__ st, int t,
                                             float* __restrict__ plc, Aff& inc,
                                             float* __restrict__ ish_slot)
{
    const int j0 = 8 * t;
    float l_a = dnbl(st[SPAD(3064 + j0)]);
    float l_b = dnbl(st[SPAD(3064 + j0 + 1)]);
    float d_a = dnd (st[SPAD(2042 + j0)]);
    float ctp = clipE((l_a * l_a + l_b * l_b - d_a * d_a) * rcp_a(2.0f * l_a * l_b));
    float stp = sqt_a((1.0f - ctp) * (1.0f + ctp));
    if (t == 0) {
        ish_slot[0] = l_a; ish_slot[1] = l_b; ish_slot[2] = ctp; ish_slot[3] = stp;
    }
#pragma unroll
    for (int jj = 0; jj < 8; ++jj) {
        const int j = j0 + jj;
        float l_c = dnbl(st[SPAD(3064 + j + 2)]);
        float d_b = dnd (st[SPAD(2042 + j + 1)]);
        float ctc = clipE((l_b * l_b + l_c * l_c - d_b * d_b) * rcp_a(2.0f * l_b * l_c));
        float stc = sqt_a((1.0f - ctc) * (1.0f + ctc));

        float s0 = st[SPAD(2 * j)];
        float s1 = st[SPAD(2 * j + 1)];
        float h2 = s0 * s0 + s1 * s1;
        float cch, sch;
        if (h2 < 1e-30f) { cch = 1.0f; sch = 0.0f; }
        else { float rh = rsq_a(h2); cch = s1 * rh; sch = s0 * rh; }

        float sbc = l_b * rcp_a(l_b + EPSF);
        float cr  = l_a * sbc * stp;
        float sn  = cr * rcp_a(cr + EPSF);
        float sm  = sn * sbc;

        float wx = -l_c * ctc * sbc;
        float wy =  l_c * stc * cch * sm;
        float wz =  l_c * stc * sch * sn;
        if (j >= NSTEP) { ctc = -1.f; stc = 0.f; cch = 1.f; sch = 0.f; wx = wy = wz = 0.f; }

        Aff G;
        G.m[0] = -ctc;      G.m[1] = stc * cch;  G.m[2] = stc * sch;
        G.m[3] = -stc;      G.m[4] = -ctc * cch; G.m[5] = -ctc * sch;
        G.m[6] = 0.f;       G.m[7] = -sch;       G.m[8] = cch;
        G.p[0] = wx; G.p[1] = wy; G.p[2] = wz;

        if (jj == 0) inc = G;
        else { Aff n; compose(inc, G, n); inc = n; }

        plc[(jj * 3 + 0) * 128 + t] = inc.p[0];
        plc[(jj * 3 + 1) * 128 + t] = inc.p[1];
        plc[(jj * 3 + 2) * 128 + t] = inc.p[2];

        l_a = l_b; l_b = l_c; ctp = ctc; stp = stc;
    }
}

// ---------------------------------------------------------------------------
// Fused kernel: 256 threads/row. Half 0 = pred, half 1 = targ.
// Scan = warp-shuffle (no barriers) + one cross-warp combine.
// ---------------------------------------------------------------------------
__global__ void __launch_bounds__(256) fused_kernel(const float* __restrict__ pred,
                                                    const float* __restrict__ targ,
                                                    float* __restrict__ out)
{
    extern __shared__ float smem[];
    float* pl   = smem;
    float* stP  = smem + STG_OFF;
    float* stT  = stP + STG_F;
    float* agg  = smem + AGG_OFF;
    float* ish  = smem + ISH_OFF;
    float* wred = smem + WRED_OFF;

    const int tid  = threadIdx.x;
    const int half = tid >> 7;         // 0 = pred, 1 = targ
    const int t    = tid & 127;
    const int lane = tid & 31;
    const int w    = (tid >> 5) & 3;   // warp within half
    const int row  = blockIdx.x;
    const float* vp = pred + (size_t)row * LV;
    const float* vt = targ + (size_t)row * LV;

    // ---- stage inputs (coalesced); pred clipped at stage ----
    for (int i = tid; i < 4104; i += 256) {
        float a = (i < LV) ? clip1(__ldg(vp + i)) : 0.f;
        float b = (i < LV) ? __ldg(vt + i) : 0.f;
        stP[SPAD(i)] = a;
        stT[SPAD(i)] = b;
    }
    __syncthreads();

    // ---- phase 1: one chain per half ----
    const float* st = half ? stT : stP;
    float* plc = pl + half * (24 * 128);
    Aff inc;
    chain_phase1(st, t, plc, inc, ish + 4 * half);

    // ---- phase 2a: in-warp inclusive scan (register shuffles, no barriers) ----
#pragma unroll
    for (int d = 1; d < 32; d <<= 1) {
        Aff o;
        shfl_up_aff(inc, o, d);
        if (lane >= d) { Aff n; compose(o, inc, n); inc = n; }
    }

    // ---- phase 2b: cross-warp combine ----
    float* aggw = agg + (half * 4 + w) * 12;
    if (lane == 31) {
#pragma unroll
        for (int k = 0; k < 9; ++k) aggw[k] = inc.m[k];
#pragma unroll
        for (int k = 0; k < 3; ++k) aggw[9 + k] = inc.p[k];
    }
    // in-warp exclusive prefix (before the barrier; register-only)
    Aff exw;
    {
        Aff o;
        shfl_up_aff(inc, o, 1);
        if (lane == 0) identityA(exw); else exw = o;
    }
    __syncthreads();

    // exclusive prefix of warp aggregates (<=3 composes, broadcast smem reads)
    Aff wex;
    identityA(wex);
    const float* aggbase = agg + half * 48;
#pragma unroll
    for (int ww = 0; ww < 3; ++ww) {
        if (ww < w) {
            Aff A;
#pragma unroll
            for (int k = 0; k < 9; ++k) A.m[k] = aggbase[ww * 12 + k];
#pragma unroll
            for (int k = 0; k < 3; ++k) A.p[k] = aggbase[ww * 12 + 9 + k];
            Aff n; compose(wex, A, n); wex = n;
        }
    }
    Aff ex;
    compose(wex, exw, ex);

    // ---- globalize with this chain's initial frame S = (F2, p2) ----
    float l0 = ish[4 * half + 0], l1 = ish[4 * half + 1];
    float c0 = ish[4 * half + 2], s0i = ish[4 * half + 3];
    Aff S;
    S.m[0] = -c0;  S.m[1] = s0i;  S.m[2] = 0.f;
    S.m[3] = -s0i; S.m[4] = -c0;  S.m[5] = 0.f;
    S.m[6] = 0.f;  S.m[7] = 0.f;  S.m[8] = 1.f;
    S.p[0] = fmaf(-l1, c0, l0); S.p[1] = l1 * s0i; S.p[2] = 0.f;
    Aff R;
    compose(S, ex, R);

    // ---- phase 3a: overwrite pl with GLOBAL positions (own slots) ----
#pragma unroll
    for (int jj = 0; jj < 8; ++jj) {
        float lx = plc[(jj * 3 + 0) * 128 + t];
        float ly = plc[(jj * 3 + 1) * 128 + t];
        float lz = plc[(jj * 3 + 2) * 128 + t];
        float e[3];
        mv(R.m, lx, ly, lz, e);
        plc[(jj * 3 + 0) * 128 + t] = R.p[0] + e[0];
        plc[(jj * 3 + 1) * 128 + t] = R.p[1] + e[1];
        plc[(jj * 3 + 2) * 128 + t] = R.p[2] + e[2];
    }
    __syncthreads();

    // ---- phase 3b: all 256 threads compute pred-targ diffs ----
    float acc = 0.f;
    if (tid == 0) {   // atoms 1 and 2 (atom 0 identical zero)
        float l0P = ish[0], l1P = ish[1], ct0 = ish[2], st0 = ish[3];
        float l0T = ish[4], l1T = ish[5], ct1 = ish[6], st1 = ish[7];
        float d1  = l0P - l0T;
        float d2x = fmaf(-l1P, ct0, l0P) - fmaf(-l1T, ct1, l0T);
        float d2y = l1P * st0 - l1T * st1;
        acc = fmaf(d1, d1, fmaf(d2x, d2x, d2y * d2y));
    }
#pragma unroll
    for (int i = 0; i < 4; ++i) {
        int idx = tid + 256 * i;           // (jj, t2) pair
        int jj  = idx >> 7;
        int t2  = idx & 127;
        if (8 * t2 + jj < NSTEP) {
            float fx = pl[(jj * 3 + 0) * 128 + t2] - pl[(24 * 128) + (jj * 3 + 0) * 128 + t2];
            float fy = pl[(jj * 3 + 1) * 128 + t2] - pl[(24 * 128) + (jj * 3 + 1) * 128 + t2];
            float fz = pl[(jj * 3 + 2) * 128 + t2] - pl[(24 * 128) + (jj * 3 + 2) * 128 + t2];
            acc = fmaf(fx, fx, acc);
            acc = fmaf(fy, fy, acc);
            acc = fmaf(fz, fz, acc);
        }
    }

    // ---- reduce + global accumulate; last block finalizes + self-resets ----
#pragma unroll
    for (int off = 16; off > 0; off >>= 1)
        acc += __shfl_xor_sync(0xffffffffu, acc, off);
    if ((tid & 31) == 0) wred[tid >> 5] = acc;
    __syncthreads();
    if (tid == 0) {
        float tot = 0.f;
#pragma unroll
        for (int ww = 0; ww < 8; ++ww) tot += wred[ww];
        atomicAdd(&g_acc, (double)tot);
        __threadfence();
        unsigned old = atomicAdd(&g_count, 1u);
        if (old == (unsigned)(gridDim.x - 1)) {
            double total;
            asm volatile("ld.global.cg.f64 %0, [%1];" : "=d"(total) : "l"(&g_acc));
            out[0] = (float)(total * (1.0 / (2048.0 * 1024.0 * 3.0)));
            asm volatile("st.global.cg.f64 [%0], %1;" :: "l"(&g_acc), "d"(0.0));
            __threadfence();
            asm volatile("st.global.cg.u32 [%0], %1;" :: "l"(&g_count), "r"(0u));
        }
    }
}

extern "C" void kernel_launch(void* const* d_in, const int* in_sizes, int n_in,
                              void* d_out, int out_size)
{
    const float* pred = (const float*)d_in[0];
    const float* targ = (const float*)d_in[1];
    float* out = (float*)d_out;

    cudaFuncSetAttribute(fused_kernel,
                         cudaFuncAttributeMaxDynamicSharedMemorySize, SMEM_BYTES);
    fused_kernel<<<BROWS, 256, SMEM_BYTES>>>(pred, targ, out);
}

// round 17
// speedup vs baseline: 1.1217x; 1.0319x over previous
#include <cuda_runtime.h>
#include <cstdint>

#define LV     4087
#define BROWS  2048
#define NSTEP  1021
#define EPSF   1e-6f

__device__ double   g_acc   = 0.0;
__device__ unsigned g_count = 0u;

__device__ __forceinline__ float dnbl(float v) { return fmaf(v, 1.05f, 1.95f); }
__device__ __forceinline__ float dnd (float v) { return fmaf(v, 1.75f, 3.25f); }
__device__ __forceinline__ float clip1(float v) { return fminf(fmaxf(v, -1.0f), 1.0f); }
__device__ __forceinline__ float clipE(float v) { return fminf(fmaxf(v, -1.0f + EPSF), 1.0f - EPSF); }
__device__ __forceinline__ float rcp_a(float x){ float y; asm("rcp.approx.f32 %0,%1;":"=f"(y):"f"(x)); return y; }
__device__ __forceinline__ float rsq_a(float x){ float y; asm("rsqrt.approx.f32 %0,%1;":"=f"(y):"f"(x)); return y; }
__device__ __forceinline__ float sqt_a(float x){ float y; asm("sqrt.approx.f32 %0,%1;":"=f"(y):"f"(x)); return y; }

// ---------------------------------------------------------------------------
// Affine algebra (col-major m[3c+r]); (L∘R) = (R_L·R_R, t_L + R_L·t_R)
// ---------------------------------------------------------------------------
struct Aff { float m[9]; float p[3]; };

__device__ __forceinline__ void mv(const float* m, float x, float y, float z, float* o)
{
    o[0] = fmaf(m[0], x, fmaf(m[3], y, m[6] * z));
    o[1] = fmaf(m[1], x, fmaf(m[4], y, m[7] * z));
    o[2] = fmaf(m[2], x, fmaf(m[5], y, m[8] * z));
}
__device__ __forceinline__ void compose(const Aff& L, const Aff& R, Aff& O)
{
    mv(L.m, R.m[0], R.m[1], R.m[2], O.m + 0);
    mv(L.m, R.m[3], R.m[4], R.m[5], O.m + 3);
    mv(L.m, R.m[6], R.m[7], R.m[8], O.m + 6);
    float tv[3];
    mv(L.m, R.p[0], R.p[1], R.p[2], tv);
    O.p[0] = L.p[0] + tv[0];
    O.p[1] = L.p[1] + tv[1];
    O.p[2] = L.p[2] + tv[2];
}
__device__ __forceinline__ void identityA(Aff& X)
{
    X.m[0] = 1.f; X.m[1] = 0.f; X.m[2] = 0.f;
    X.m[3] = 0.f; X.m[4] = 1.f; X.m[5] = 0.f;
    X.m[6] = 0.f; X.m[7] = 0.f; X.m[8] = 1.f;
    X.p[0] = X.p[1] = X.p[2] = 0.f;
}
__device__ __forceinline__ void shfl_up_aff(const Aff& in, Aff& o, int d)
{
#pragma unroll
    for (int k = 0; k < 9; ++k) o.m[k] = __shfl_up_sync(0xffffffffu, in.m[k], d);
#pragma unroll
    for (int k = 0; k < 3; ++k) o.p[k] = __shfl_up_sync(0xffffffffu, in.p[k], d);
}

// ---------------------------------------------------------------------------
// Shared memory (floats):
//   pl [48*128], scP/scT [2184], dP/dT [1160], blP/blT [1160], agg[96], ish[8], wred[8]
// Region-local padding: addr(i) = i + (i>>4) for sc, i + (i>>3) for d/bl.
// Reads become base*t + constant: sc 17t+2k, d/bl 9t+o (+carry const). All
// strides (17, 9) are coprime to 32 -> conflict-free.
// ---------------------------------------------------------------------------
#define PL_F     (48 * 128)
#define SC_F     2184
#define D_F      1160
#define BL_F     1160
#define SCP_OFF  PL_F
#define SCT_OFF  (SCP_OFF + SC_F)
#define DP_OFF   (SCT_OFF + SC_F)
#define DT_OFF   (DP_OFF + D_F)
#define BLP_OFF  (DT_OFF + D_F)
#define BLT_OFF  (BLP_OFF + BL_F)
#define AGG_OFF  (BLT_OFF + BL_F)
#define ISH_OFF  (AGG_OFF + 96)
#define WRED_OFF (ISH_OFF + 8)
#define SMEM_F   (WRED_OFF + 8)
#define SMEM_BYTES (SMEM_F * 4)

// ---------------------------------------------------------------------------
// Phase 1 for one chain: coefficients + sparse compose-with-G + stash.
// G cols: g0=(-ct, st*cX, st*sX), g1=(-st, -ct*cX, -ct*sX), g2=(0, -sX, cX)
// O.col0 = nct*L0 + stc*v ; O.col1 = nst*L0 + nct*v ; O.col2 = cch*L2 - sch*L1
// with v = cch*L1 + sch*L2 ;  p' = p + L*w.
// ---------------------------------------------------------------------------
__device__ __forceinline__ void chain_phase1(const float* __restrict__ scb,
                                             const float* __restrict__ db,
                                             const float* __restrict__ blb,
                                             int t, float* __restrict__ plc,
                                             Aff& inc, float* __restrict__ ish_slot)
{
    const int sb = 17 * t;
    const int nb = 9 * t;

    float l_a = dnbl(blb[nb]);
    float l_b = dnbl(blb[nb + 1]);
    float d_a = dnd (db[nb]);
    float ctp = clipE((l_a * l_a + l_b * l_b - d_a * d_a) * rcp_a(2.0f * l_a * l_b));
    float stp = sqt_a((1.0f - ctp) * (1.0f + ctp));
    if (t == 0) {
        ish_slot[0] = l_a; ish_slot[1] = l_b; ish_slot[2] = ctp; ish_slot[3] = stp;
    }
#pragma unroll
    for (int jj = 0; jj < 8; ++jj) {
        const int j  = 8 * t + jj;
        const int od = (jj + 1) + ((jj + 1) >> 3);   // compile-time constants
        const int ob = (jj + 2) + ((jj + 2) >> 3);
        float d_b = dnd (db[nb + od]);
        float l_c = dnbl(blb[nb + ob]);
        float ctc = clipE((l_b * l_b + l_c * l_c - d_b * d_b) * rcp_a(2.0f * l_b * l_c));
        float stc = sqt_a((1.0f - ctc) * (1.0f + ctc));

        float s0 = scb[sb + 2 * jj];
        float s1 = scb[sb + 2 * jj + 1];
        float h2 = s0 * s0 + s1 * s1;
        float cch, sch;
        if (h2 < 1e-30f) { cch = 1.0f; sch = 0.0f; }
        else { float rh = rsq_a(h2); cch = s1 * rh; sch = s0 * rh; }

        float sbc = l_b * rcp_a(l_b + EPSF);
        float cr  = l_a * sbc * stp;
        float sn  = cr * rcp_a(cr + EPSF);
        float sm  = sn * sbc;

        float wx = -l_c * ctc * sbc;
        float wy =  l_c * stc * cch * sm;
        float wz =  l_c * stc * sch * sn;
        if (j >= NSTEP) { ctc = -1.f; stc = 0.f; cch = 1.f; sch = 0.f; wx = wy = wz = 0.f; }

        float nct = -ctc, nst = -stc, nsh = -sch;
        if (jj == 0) {
            inc.m[0] = nct;       inc.m[1] = stc * cch;  inc.m[2] = stc * sch;
            inc.m[3] = nst;       inc.m[4] = nct * cch;  inc.m[5] = nct * sch;
            inc.m[6] = 0.f;       inc.m[7] = nsh;        inc.m[8] = cch;
            inc.p[0] = wx; inc.p[1] = wy; inc.p[2] = wz;
        } else {
            // p' = p + L*w  (uses OLD columns; compute first)
            float tp0 = fmaf(wx, inc.m[0], fmaf(wy, inc.m[3], wz * inc.m[6]));
            float tp1 = fmaf(wx, inc.m[1], fmaf(wy, inc.m[4], wz * inc.m[7]));
            float tp2 = fmaf(wx, inc.m[2], fmaf(wy, inc.m[5], wz * inc.m[8]));
            float v0 = fmaf(cch, inc.m[3], sch * inc.m[6]);
            float v1 = fmaf(cch, inc.m[4], sch * inc.m[7]);
            float v2 = fmaf(cch, inc.m[5], sch * inc.m[8]);
            float c20 = fmaf(cch, inc.m[6], nsh * inc.m[3]);
            float c21 = fmaf(cch, inc.m[7], nsh * inc.m[4]);
            float c22 = fmaf(cch, inc.m[8], nsh * inc.m[5]);
            float c00 = fmaf(nct, inc.m[0], stc * v0);
            float c01 = fmaf(nct, inc.m[1], stc * v1);
            float c02 = fmaf(nct, inc.m[2], stc * v2);
            float c10 = fmaf(nst, inc.m[0], nct * v0);
            float c11 = fmaf(nst, inc.m[1], nct * v1);
            float c12 = fmaf(nst, inc.m[2], nct * v2);
            inc.m[0] = c00; inc.m[1] = c01; inc.m[2] = c02;
            inc.m[3] = c10; inc.m[4] = c11; inc.m[5] = c12;
            inc.m[6] = c20; inc.m[7] = c21; inc.m[8] = c22;
            inc.p[0] += tp0; inc.p[1] += tp1; inc.p[2] += tp2;
        }

        plc[(jj * 3 + 0) * 128 + t] = inc.p[0];
        plc[(jj * 3 + 1) * 128 + t] = inc.p[1];
        plc[(jj * 3 + 2) * 128 + t] = inc.p[2];

        l_a = l_b; l_b = l_c; ctp = ctc; stp = stc;
    }
}

// ---------------------------------------------------------------------------
// Fused kernel: 256 threads/row. Half 0 = pred, half 1 = targ.
// ---------------------------------------------------------------------------
__global__ void __launch_bounds__(256) fused_kernel(const float* __restrict__ pred,
                                                    const float* __restrict__ targ,
                                                    float* __restrict__ out)
{
    extern __shared__ float smem[];
    float* pl   = smem;
    float* scP  = smem + SCP_OFF;
    float* scT  = smem + SCT_OFF;
    float* dP   = smem + DP_OFF;
    float* dT   = smem + DT_OFF;
    float* blP  = smem + BLP_OFF;
    float* blT  = smem + BLT_OFF;
    float* agg  = smem + AGG_OFF;
    float* ish  = smem + ISH_OFF;
    float* wred = smem + WRED_OFF;

    const int tid  = threadIdx.x;
    const int half = tid >> 7;         // 0 = pred, 1 = targ
    const int t    = tid & 127;
    const int lane = tid & 31;
    const int w    = (tid >> 5) & 3;   // warp within half
    const int row  = blockIdx.x;
    const float* vp = pred + (size_t)row * LV;
    const float* vt = targ + (size_t)row * LV;

    // ---- stage inputs into region-split padded buffers (coalesced) ----
    for (int i = tid; i < LV; i += 256) {
        float a = clip1(__ldg(vp + i));
        float b = __ldg(vt + i);
        if (i < 2048) {                       // sc region (guard reads to 2047)
            int ad = i + (i >> 4);
            scP[ad] = a; scT[ad] = b;
        }
        if (i >= 2042 && i < 3067) {          // d region (guard to linear 1024)
            int i2 = i - 2042;
            int ad = i2 + (i2 >> 3);
            dP[ad] = a; dT[ad] = b;
        }
        if (i >= 3064) {                      // bl region
            int i3 = i - 3064;
            int ad = i3 + (i3 >> 3);
            blP[ad] = a; blT[ad] = b;
        }
    }
    __syncthreads();

    // ---- phase 1: one chain per half ----
    float* plc = pl + half * (24 * 128);
    Aff inc;
    if (half == 0) chain_phase1(scP, dP, blP, t, plc, inc, ish);
    else           chain_phase1(scT, dT, blT, t, plc, inc, ish + 4);

    // ---- phase 2a: in-warp inclusive scan (register shuffles) ----
#pragma unroll
    for (int d = 1; d < 32; d <<= 1) {
        Aff o;
        shfl_up_aff(inc, o, d);
        if (lane >= d) { Aff n; compose(o, inc, n); inc = n; }
    }

    // ---- phase 2b: cross-warp combine ----
    float* aggw = agg + (half * 4 + w) * 12;
    if (lane == 31) {
#pragma unroll
        for (int k = 0; k < 9; ++k) aggw[k] = inc.m[k];
#pragma unroll
        for (int k = 0; k < 3; ++k) aggw[9 + k] = inc.p[k];
    }
    Aff exw;
    {
        Aff o;
        shfl_up_aff(inc, o, 1);
        if (lane == 0) identityA(exw); else exw = o;
    }
    __syncthreads();

    Aff wex;
    identityA(wex);
    const float* aggbase = agg + half * 48;
#pragma unroll
    for (int ww = 0; ww < 3; ++ww) {
        if (ww < w) {
            Aff A;
#pragma unroll
            for (int k = 0; k < 9; ++k) A.m[k] = aggbase[ww * 12 + k];
#pragma unroll
            for (int k = 0; k < 3; ++k) A.p[k] = aggbase[ww * 12 + 9 + k];
            Aff n; compose(wex, A, n); wex = n;
        }
    }
    Aff ex;
    compose(wex, exw, ex);

    // ---- globalize with this chain's initial frame S = (F2, p2) ----
    float l0 = ish[4 * half + 0], l1 = ish[4 * half + 1];
    float c0 = ish[4 * half + 2], s0i = ish[4 * half + 3];
    Aff S;
    S.m[0] = -c0;  S.m[1] = s0i;  S.m[2] = 0.f;
    S.m[3] = -s0i; S.m[4] = -c0;  S.m[5] = 0.f;
    S.m[6] = 0.f;  S.m[7] = 0.f;  S.m[8] = 1.f;
    S.p[0] = fmaf(-l1, c0, l0); S.p[1] = l1 * s0i; S.p[2] = 0.f;
    Aff R;
    compose(S, ex, R);

    // ---- phase 3a: overwrite pl with GLOBAL positions (own slots) ----
#pragma unroll
    for (int jj = 0; jj < 8; ++jj) {
        float lx = plc[(jj * 3 + 0) * 128 + t];
        float ly = plc[(jj * 3 + 1) * 128 + t];
        float lz = plc[(jj * 3 + 2) * 128 + t];
        float e[3];
        mv(R.m, lx, ly, lz, e);
        plc[(jj * 3 + 0) * 128 + t] = R.p[0] + e[0];
        plc[(jj * 3 + 1) * 128 + t] = R.p[1] + e[1];
        plc[(jj * 3 + 2) * 128 + t] = R.p[2] + e[2];
    }
    __syncthreads();

    // ---- phase 3b: all 256 threads compute pred-targ diffs ----
    float acc = 0.f;
    if (tid == 0) {   // atoms 1 and 2 (atom 0 identical zero)
        float l0P = ish[0], l1P = ish[1], ct0 = ish[2], st0 = ish[3];
        float l0T = ish[4], l1T = ish[5], ct1 = ish[6], st1 = ish[7];
        float d1  = l0P - l0T;
        float d2x = fmaf(-l1P, ct0, l0P) - fmaf(-l1T, ct1, l0T);
        float d2y = l1P * st0 - l1T * st1;
        acc = fmaf(d1, d1, fmaf(d2x, d2x, d2y * d2y));
    }
#pragma unroll
    for (int i = 0; i < 4; ++i) {
        int idx = tid + 256 * i;           // (jj, t2) pair
        int jj  = idx >> 7;
        int t2  = idx & 127;
        if (8 * t2 + jj < NSTEP) {
            float fx = pl[(jj * 3 + 0) * 128 + t2] - pl[(24 * 128) + (jj * 3 + 0) * 128 + t2];
            float fy = pl[(jj * 3 + 1) * 128 + t2] - pl[(24 * 128) + (jj * 3 + 1) * 128 + t2];
            float fz = pl[(jj * 3 + 2) * 128 + t2] - pl[(24 * 128) + (jj * 3 + 2) * 128 + t2];
            acc = fmaf(fx, fx, acc);
            acc = fmaf(fy, fy, acc);
            acc = fmaf(fz, fz, acc);
        }
    }

    // ---- reduce + global accumulate; last block finalizes + self-resets ----
#pragma unroll
    for (int off = 16; off > 0; off >>= 1)
        acc += __shfl_xor_sync(0xffffffffu, acc, off);
    if ((tid & 31) == 0) wred[tid >> 5] = acc;
    __syncthreads();
    if (tid == 0) {
        float tot = 0.f;
#pragma unroll
        for (int ww = 0; ww < 8; ++ww) tot += wred[ww];
        atomicAdd(&g_acc, (double)tot);
        __threadfence();
        unsigned old = atomicAdd(&g_count, 1u);
        if (old == (unsigned)(gridDim.x - 1)) {
            double total;
            asm volatile("ld.global.cg.f64 %0, [%1];" : "=d"(total) : "l"(&g_acc));
            out[0] = (float)(total * (1.0 / (2048.0 * 1024.0 * 3.0)));
            asm volatile("st.global.cg.f64 [%0], %1;" :: "l"(&g_acc), "d"(0.0));
            __threadfence();
            asm volatile("st.global.cg.u32 [%0], %1;" :: "l"(&g_count), "r"(0u));
        }
    }
}

extern "C" void kernel_launch(void* const* d_in, const int* in_sizes, int n_in,
                              void* d_out, int out_size)
{
    const float* pred = (const float*)d_in[0];
    const float* targ = (const float*)d_in[1];
    float* out = (float*)d_out;

    cudaFuncSetAttribute(fused_kernel,
                         cudaFuncAttributeMaxDynamicSharedMemorySize, SMEM_BYTES);
    fused_kernel<<<BROWS, 256, SMEM_BYTES>>>(pred, targ, out);
}